// round 8
// baseline (speedup 1.0000x reference)
#include <cuda_runtime.h>
#include <cuda_bf16.h>

#define FEAT 64
#define EPR 64              // edges per 16-lane row
#define ROWS_PER_BLOCK 16   // 256 threads / 16 lanes
#define THREADS 256
#define GRID_SEGSUM 1184    // 148 SMs * 8 CTAs -> single persistent wave

// K0: zero exactly the nodes that will receive atomicAdd flushes, i.e. nodes
// whose segment crosses a chunk boundary. Re-run every call -> idempotent.
__global__ void __launch_bounds__(THREADS)
zero_boundary_kernel(const int* __restrict__ seg,
                     float4* __restrict__ out4,   // [N*16]
                     int n_rows, int n_edges) {
    int b    = blockIdx.x * ROWS_PER_BLOCK + (threadIdx.x >> 4) + 1;
    int lane = threadIdx.x & 15;
    if (b >= n_rows) return;
    int e = b * EPR;
    if (e >= n_edges) return;
    int s_prev = __ldg(&seg[e - 1]);
    int s_cur  = __ldg(&seg[e]);
    if (s_prev == s_cur)
        out4[(size_t)s_cur * 16 + lane] = make_float4(0.f, 0.f, 0.f, 0.f);
}

// K1: weighted segment-sum over sorted segment_ids, bias fused.
// Persistent: each block grid-strides over 64-edge rows. Within a row,
// 16 lanes each own 4 features. Complete runs owned by this row -> one plain
// STG.128 of acc+bias (sole writer, idempotent). Boundary-crossing segments ->
// atomicAdd into the K0-zeroed node; the segment's START owner adds bias.
// Empty nodes (gaps in sorted ids) -> plain bias stores.
__global__ void __launch_bounds__(THREADS)
segsum_kernel(const float4* __restrict__ feats,   // [E,16] float4 view of [E,64]
              const float*  __restrict__ attn,    // [E]
              const int*    __restrict__ seg,     // [E] sorted
              float* __restrict__ out,            // [N,64]
              const float4* __restrict__ bias4,   // [16]
              int n_edges, int n_nodes, int n_rows) {
    int lane = threadIdx.x & 15;
    int row0 = blockIdx.x * ROWS_PER_BLOCK + (threadIdx.x >> 4);
    int rstride = gridDim.x * ROWS_PER_BLOCK;

    float4 bia = __ldg(&bias4[lane]);

    for (int row = row0; row < n_rows; row += rstride) {
        int e0 = row * EPR;
        int e_end = e0 + EPR;
        if (e_end > n_edges) e_end = n_edges;

        int  cur   = __ldg(&seg[e0]);
        bool first = true;
        bool owned_head = (e0 == 0) || (__ldg(&seg[e0 - 1]) != cur);
        float4 acc = make_float4(0.f, 0.f, 0.f, 0.f);

        // leading empty nodes [0, seg[0]) — only the very first row
        if (e0 == 0) {
            for (int m = 0; m < cur; ++m)
                ((float4*)(out + (size_t)m * FEAT))[lane] = bia;
        }

        #pragma unroll 4
        for (int e = e0; e < e_end; ++e) {
            int   s = __ldg(&seg[e]);
            float a = __ldg(&attn[e]);
            float4 f = __ldg(&feats[(size_t)e * 16 + lane]);

            if (s != cur) {
                if (first && !owned_head) {
                    // continuation of a segment started earlier: atomic, no bias
                    float* o = out + (size_t)cur * FEAT + lane * 4;
                    atomicAdd(o + 0, acc.x); atomicAdd(o + 1, acc.y);
                    atomicAdd(o + 2, acc.z); atomicAdd(o + 3, acc.w);
                } else {
                    // run started and ended here: sole writer, bias fused
                    float4 v = make_float4(acc.x + bia.x, acc.y + bia.y,
                                           acc.z + bia.z, acc.w + bia.w);
                    ((float4*)(out + (size_t)cur * FEAT))[lane] = v;
                }
                for (int m = cur + 1; m < s; ++m)
                    ((float4*)(out + (size_t)m * FEAT))[lane] = bia;
                first = false;
                acc = make_float4(0.f, 0.f, 0.f, 0.f);
                cur = s;
            }
            acc.x = fmaf(a, f.x, acc.x);
            acc.y = fmaf(a, f.y, acc.y);
            acc.z = fmaf(a, f.z, acc.z);
            acc.w = fmaf(a, f.w, acc.w);
        }

        // tail flush for this row
        bool has_next = (e_end < n_edges);
        int  next_s   = has_next ? __ldg(&seg[e_end]) : n_nodes;
        bool tail_shared = has_next && (next_s == cur);

        if (first && !owned_head) {
            // row lies inside a larger segment: pure continuation partial
            float* o = out + (size_t)cur * FEAT + lane * 4;
            atomicAdd(o + 0, acc.x); atomicAdd(o + 1, acc.y);
            atomicAdd(o + 2, acc.z); atomicAdd(o + 3, acc.w);
        } else if (tail_shared) {
            // segment STARTS here and crosses out: owner adds bias via atomic
            float* o = out + (size_t)cur * FEAT + lane * 4;
            atomicAdd(o + 0, acc.x + bia.x); atomicAdd(o + 1, acc.y + bia.y);
            atomicAdd(o + 2, acc.z + bia.z); atomicAdd(o + 3, acc.w + bia.w);
        } else {
            // segment starts and ends within this row: sole writer
            float4 v = make_float4(acc.x + bia.x, acc.y + bia.y,
                                   acc.z + bia.z, acc.w + bia.w);
            ((float4*)(out + (size_t)cur * FEAT))[lane] = v;
        }

        // trailing empty nodes up to the next row's first segment (or N)
        for (int m = cur + 1; m < next_s; ++m)
            ((float4*)(out + (size_t)m * FEAT))[lane] = bia;
    }
}

extern "C" void kernel_launch(void* const* d_in, const int* in_sizes, int n_in,
                              void* d_out, int out_size) {
    // metadata order: nodes[0] (unused), neighbor_feats[1], attention[2],
    //                 bias[3], segment_ids[4]
    const float* feats = (const float*)d_in[1];
    const float* attn  = (const float*)d_in[2];
    const float* bias  = (const float*)d_in[3];
    const int*   seg   = (const int*)d_in[4];
    float* out = (float*)d_out;

    int n_edges = in_sizes[2];          // attention element count = E
    int n_nodes = out_size / FEAT;      // N
    int n_rows  = (n_edges + EPR - 1) / EPR;

    // K0: zero the future atomic targets (boundary-crossing nodes)
    {
        int n_b = n_rows;  // boundaries 1..n_rows-1 handled inside
        int blocks = (n_b + ROWS_PER_BLOCK - 1) / ROWS_PER_BLOCK;
        zero_boundary_kernel<<<blocks, THREADS>>>(seg, (float4*)out,
                                                  n_rows, n_edges);
    }

    // K1: persistent single-wave weighted segment-sum
    {
        int blocks = GRID_SEGSUM;
        int max_blocks = (n_rows + ROWS_PER_BLOCK - 1) / ROWS_PER_BLOCK;
        if (blocks > max_blocks) blocks = max_blocks;
        segsum_kernel<<<blocks, THREADS>>>((const float4*)feats, attn, seg, out,
                                           (const float4*)bias,
                                           n_edges, n_nodes, n_rows);
    }
}